// round 15
// baseline (speedup 1.0000x reference)
#include <cuda_runtime.h>
#include <cuda_bf16.h>
#include <math.h>
#include <stdint.h>

// ---------------------------------------------------------------------------
// problem constants
// ---------------------------------------------------------------------------
#define BS     16384
#define NC     2000
#define NPADC  2048
#define DIM    512
#define TMR    128              // M rows per tile
#define NCH    256              // classes per N chunk
#define BK     64               // K per stage
#define ROWB   144              // padded smem row stride (72 bf16)
#define ABLK   (128 * ROWB)     // 18432
#define BBLK   (256 * ROWB)     // 36864
#define STG    (ABLK + BBLK)    // 55296
#define NSTG   3
#define DSMEM  (NSTG * STG)     // 165888
#define GRID   148              // persistent CTAs (one per SM)
#define NUNITS 1024             // 128 m-tiles * 8 n-chunks
#define NSLOT  8                // 8 n-chunk partials per row (warpN pre-combined)
#define NRB    64               // reduce blocks
#define NROWS  (BS + NPADC)     // prep rows (f then w)
#define NWARPS (GRID * 8)       // 1184 prep warps
#define K20    28.853900817779268f   // 20 / ln(2)

// ---------------------------------------------------------------------------
// device scratch (allocation-free)
// ---------------------------------------------------------------------------
__device__ float g_ta[BS];
__device__ float g_psum[NSLOT * BS];    // [slot][row] partial exp-sums
__device__ float g_pmax[NSLOT * BS];    // [slot][row] partial maxima
__device__ int   g_pidx[NSLOT * BS];    // [slot][row] partial argmax
__device__ float g_blkl[NRB];           // per-block loss partials
__device__ float g_blkc[NRB];           // per-block acc partials
__device__ unsigned int g_ctr;          // reduce completion counter (zero-init)
__device__ unsigned int g_bar;          // grid barrier arrivals (zero-init)
__device__ unsigned int g_done;         // exit counter for barrier reset
__device__ __nv_bfloat16 g_fb[(size_t)BS * DIM];
__device__ __nv_bfloat16 g_wb[(size_t)NPADC * DIM];

// ---------------------------------------------------------------------------
// helpers
// ---------------------------------------------------------------------------
static __device__ __forceinline__ uint32_t sm2u(const void* p) {
    uint32_t a;
    asm("{ .reg .u64 t; cvta.to.shared.u64 t, %1; cvt.u32.u64 %0, t; }"
        : "=r"(a) : "l"(p));
    return a;
}

static __device__ __forceinline__ float ex2f(float x) {
    float y;
    asm("ex2.approx.f32 %0, %1;" : "=f"(y) : "f"(x));
    return y;
}

#define LDSM4(r0, r1, r2, r3, addr) \
    asm volatile("ldmatrix.sync.aligned.m8n8.x4.shared.b16 {%0,%1,%2,%3}, [%4];" \
                 : "=r"(r0), "=r"(r1), "=r"(r2), "=r"(r3) : "r"(addr))

#define MMA16816(d, a, b) \
    asm volatile("mma.sync.aligned.m16n8k16.row.col.f32.bf16.bf16.f32 " \
                 "{%0,%1,%2,%3}, {%4,%5,%6,%7}, {%8,%9}, {%0,%1,%2,%3};" \
                 : "+f"((d)[0]), "+f"((d)[1]), "+f"((d)[2]), "+f"((d)[3]) \
                 : "r"((a)[0]), "r"((a)[1]), "r"((a)[2]), "r"((a)[3]), \
                   "r"((b)[0]), "r"((b)[1]))

#define CPASYNC16(dst, src) \
    asm volatile("cp.async.cg.shared.global [%0], [%1], 16;" :: "r"(dst), "l"(src))

// ---------------------------------------------------------------------------
// persistent kernel: inline prep -> grid barrier -> fused GEMM+softmax+gather
// ---------------------------------------------------------------------------
__global__ void __launch_bounds__(256, 1)
gemm_fused(const float* __restrict__ fin, const float* __restrict__ win,
           const int* __restrict__ label, const int* __restrict__ aux) {
    extern __shared__ char dsm[];
    __shared__ float sredS[4][TMR];
    __shared__ float sredM[4][TMR];
    __shared__ int   sredI[4][TMR];

    const int tid   = threadIdx.x;
    const int lane  = tid & 31;
    const int wid   = tid >> 5;
    const int warpM = wid & 1;     // rows warpM*64
    const int warpN = wid >> 1;    // cols warpN*64
    const uint32_t sbase = sm2u(dsm);
    const int cta = blockIdx.x;

    // ======================= phase 1: prep (rownorm + bf16) ===============
    for (int row = cta * 8 + wid; row < NROWS; row += NWARPS) {
        const float* x;
        __nv_bfloat16* out;
        if (row < BS) {
            x = fin + (size_t)row * DIM;
            out = g_fb + (size_t)row * DIM;
        } else {
            int wr = row - BS;
            out = g_wb + (size_t)wr * DIM;
            if (wr >= NC) {
                uint2 z; z.x = 0u; z.y = 0u;
                uint2* dp = reinterpret_cast<uint2*>(out);
                #pragma unroll
                for (int k = 0; k < 4; ++k) dp[lane + 32 * k] = z;
                continue;
            }
            x = win + (size_t)wr * DIM;
        }
        const float4* p = reinterpret_cast<const float4*>(x);
        float4 v[4];
        float s = 0.0f;
        #pragma unroll
        for (int k = 0; k < 4; ++k) {
            v[k] = p[lane + 32 * k];
            s += v[k].x * v[k].x + v[k].y * v[k].y + v[k].z * v[k].z + v[k].w * v[k].w;
        }
        #pragma unroll
        for (int o = 16; o > 0; o >>= 1) s += __shfl_xor_sync(0xffffffffu, s, o);
        float inv = 1.0f / fmaxf(sqrtf(s), 1e-12f);
        uint2* dp = reinterpret_cast<uint2*>(out);
        #pragma unroll
        for (int k = 0; k < 4; ++k) {
            __nv_bfloat162 h0 = __floats2bfloat162_rn(v[k].x * inv, v[k].y * inv);
            __nv_bfloat162 h1 = __floats2bfloat162_rn(v[k].z * inv, v[k].w * inv);
            uint2 u;
            u.x = *reinterpret_cast<uint32_t*>(&h0);
            u.y = *reinterpret_cast<uint32_t*>(&h1);
            dp[lane + 32 * k] = u;
        }
    }

    // ======================= grid-wide barrier ============================
    __syncthreads();
    if (tid == 0) {
        __threadfence();
        atomicAdd(&g_bar, 1u);
        while (*(volatile unsigned int*)&g_bar < GRID) { }
        __threadfence();
    }
    __syncthreads();

    // ======================= phase 2: fused GEMM ==========================
    const int myUnits = (NUNITS - cta + GRID - 1) / GRID;   // 7 or 6
    const int S = myUnits * 8;

    const uint32_t aoff = (uint32_t)(warpM * 64 + (lane & 15)) * ROWB
                        + (uint32_t)(lane >> 4) * 16;
    const uint32_t boff = (uint32_t)(warpN * 64 + (lane & 7) + ((lane >> 4) << 3)) * ROWB
                        + (uint32_t)((lane >> 3) & 1) * 16;

    float acc[4][8][4];            // [mt][n8][j]
    float vsum[4][2];
    float vmax[4][2];
    int   vidx[4][2];

    auto load_stage = [&](int s, int slot) {
        const int u  = cta + (s >> 3) * GRID;
        const int kb = s & 7;
        const int mtile = u & 127, nch = u >> 7;
        const uint32_t sb = sbase + (uint32_t)slot * STG;
        const __nv_bfloat16* Asrc = g_fb + (size_t)(mtile * TMR) * DIM + kb * BK;
        const __nv_bfloat16* Bsrc = g_wb + (size_t)(nch * NCH) * DIM + kb * BK;
        #pragma unroll
        for (int i = 0; i < 4; ++i) {          // A: 1024 chunks
            int ch = tid + 256 * i;
            int row = ch >> 3, c8 = ch & 7;
            CPASYNC16(sb + (uint32_t)row * ROWB + c8 * 16,
                      Asrc + (size_t)row * DIM + c8 * 8);
        }
        #pragma unroll
        for (int i = 0; i < 8; ++i) {          // B: 2048 chunks
            int ch = tid + 256 * i;
            int row = ch >> 3, c8 = ch & 7;
            CPASYNC16(sb + ABLK + (uint32_t)row * ROWB + c8 * 16,
                      Bsrc + (size_t)row * DIM + c8 * 8);
        }
        asm volatile("cp.async.commit_group;" ::: "memory");
    };

    load_stage(0, 0);
    load_stage(1, 1);

    int csSlot = 0, ldSlot = 2;
    for (int t = 0; t < S; ++t) {
        if (t + 1 < S) {
            asm volatile("cp.async.wait_group 1;" ::: "memory");
        } else {
            asm volatile("cp.async.wait_group 0;" ::: "memory");
        }
        __syncthreads();
        if (t + 2 < S) {
            load_stage(t + 2, ldSlot);
            if (++ldSlot == NSTG) ldSlot = 0;
        }

        if ((t & 7) == 0) {
            #pragma unroll
            for (int mt = 0; mt < 4; ++mt) {
                #pragma unroll
                for (int n8 = 0; n8 < 8; ++n8)
                    #pragma unroll
                    for (int j = 0; j < 4; ++j) acc[mt][n8][j] = 0.0f;
                #pragma unroll
                for (int rh = 0; rh < 2; ++rh) {
                    vsum[mt][rh] = 0.0f; vmax[mt][rh] = -1e30f; vidx[mt][rh] = -1;
                }
            }
        }

        const uint32_t sb = sbase + (uint32_t)csSlot * STG;
        if (++csSlot == NSTG) csSlot = 0;
        const uint32_t aS = sb + aoff;
        const uint32_t bS = sb + ABLK + boff;
        #pragma unroll
        for (int kk = 0; kk < 4; ++kk) {
            uint32_t Af[4][4];
            #pragma unroll
            for (int mt = 0; mt < 4; ++mt)
                LDSM4(Af[mt][0], Af[mt][1], Af[mt][2], Af[mt][3],
                      aS + (uint32_t)mt * 16 * ROWB + kk * 32);
            uint32_t Bf[8][2];
            #pragma unroll
            for (int nt = 0; nt < 4; ++nt) {
                uint32_t r0, r1, r2, r3;
                LDSM4(r0, r1, r2, r3, bS + (uint32_t)nt * 16 * ROWB + kk * 32);
                Bf[2 * nt][0] = r0;     Bf[2 * nt][1] = r1;
                Bf[2 * nt + 1][0] = r2; Bf[2 * nt + 1][1] = r3;
            }
            #pragma unroll
            for (int mt = 0; mt < 4; ++mt)
                #pragma unroll
                for (int n8 = 0; n8 < 8; ++n8)
                    MMA16816(acc[mt][n8], Af[mt], Bf[n8]);
        }

        if ((t & 7) == 7) {
            const int u = cta + (t >> 3) * GRID;
            const int mtile = u & 127, nch = u >> 7;
            const int ncBase = nch * NCH + warpN * 64;
            if (ncBase + 64 <= NC) {
                #pragma unroll
                for (int mt = 0; mt < 4; ++mt) {
                    #pragma unroll
                    for (int n8 = 0; n8 < 8; ++n8) {
                        #pragma unroll
                        for (int j = 0; j < 4; ++j) {
                            int cls = ncBase + n8 * 8 + (lane & 3) * 2 + (j & 1);
                            float v  = acc[mt][n8][j];
                            int   rh = j >> 1;
                            if (v > vmax[mt][rh]) { vmax[mt][rh] = v; vidx[mt][rh] = cls; }
                            vsum[mt][rh] += ex2f(fmaf(v, K20, -K20));
                        }
                    }
                }
            } else {
                #pragma unroll
                for (int mt = 0; mt < 4; ++mt) {
                    #pragma unroll
                    for (int n8 = 0; n8 < 8; ++n8) {
                        #pragma unroll
                        for (int j = 0; j < 4; ++j) {
                            int cls = ncBase + n8 * 8 + (lane & 3) * 2 + (j & 1);
                            if (cls < NC) {
                                float v  = acc[mt][n8][j];
                                int   rh = j >> 1;
                                if (v > vmax[mt][rh]) { vmax[mt][rh] = v; vidx[mt][rh] = cls; }
                                vsum[mt][rh] += ex2f(fmaf(v, K20, -K20));
                            }
                        }
                    }
                }
            }
            #pragma unroll
            for (int mt = 0; mt < 4; ++mt) {
                #pragma unroll
                for (int rh = 0; rh < 2; ++rh) {
                    float s = vsum[mt][rh], m = vmax[mt][rh];
                    int   ix = vidx[mt][rh];
                    #pragma unroll
                    for (int o = 1; o <= 2; o <<= 1) {
                        float so = __shfl_xor_sync(0xffffffffu, s, o);
                        float mo = __shfl_xor_sync(0xffffffffu, m, o);
                        int   io = __shfl_xor_sync(0xffffffffu, ix, o);
                        s += so;
                        if (mo > m) { m = mo; ix = io; }
                    }
                    if ((lane & 3) == 0) {
                        int r = warpM * 64 + mt * 16 + rh * 8 + (lane >> 2);
                        sredS[warpN][r] = s;
                        sredM[warpN][r] = m;
                        sredI[warpN][r] = ix;
                    }
                }
            }
            __syncthreads();
            if (tid < TMR) {
                float s = sredS[0][tid], m = sredM[0][tid];
                int   ix = sredI[0][tid];
                #pragma unroll
                for (int wn = 1; wn < 4; ++wn) {
                    s += sredS[wn][tid];
                    float mw = sredM[wn][tid];
                    if (mw > m) { m = mw; ix = sredI[wn][tid]; }
                }
                int row = mtile * TMR + tid;
                g_psum[nch * BS + row] = s;
                g_pmax[nch * BS + row] = m;
                g_pidx[nch * BS + row] = ix;
            }

            // ---- distributed gather: rows [u*16, u*16+16), 2 per warp ----
            {
                const int grow0 = u * 16 + wid * 2;
                #pragma unroll
                for (int r = 0; r < 2; ++r) {
                    const int row = grow0 + r;
                    const uint32_t* fr = reinterpret_cast<const uint32_t*>(
                        g_fb + (size_t)row * DIM);
                    uint32_t ff[8];
                    #pragma unroll
                    for (int k = 0; k < 8; ++k) ff[k] = fr[lane + 32 * k];
                    float acc6[6];
                    #pragma unroll
                    for (int c = 0; c < 6; ++c) {
                        int cls = (c == 0) ? label[row] : aux[row * 5 + c - 1];
                        const uint32_t* wr2 = reinterpret_cast<const uint32_t*>(
                            g_wb + (size_t)cls * DIM);
                        float s = 0.0f;
                        #pragma unroll
                        for (int k = 0; k < 8; ++k) {
                            uint32_t wp = wr2[lane + 32 * k];
                            float2 fa = __bfloat1622float2(
                                *reinterpret_cast<__nv_bfloat162*>(&ff[k]));
                            float2 wa = __bfloat1622float2(
                                *reinterpret_cast<__nv_bfloat162*>(&wp));
                            s = fmaf(fa.x, wa.x, s);
                            s = fmaf(fa.y, wa.y, s);
                        }
                        #pragma unroll
                        for (int o = 16; o > 0; o >>= 1)
                            s += __shfl_xor_sync(0xffffffffu, s, o);
                        acc6[c] = s;
                    }
                    if (lane == 0) {
                        float tgt  = acc6[0] * 20.0f;
                        float auxs = (acc6[1] + acc6[2] + acc6[3]
                                    + acc6[4] + acc6[5]) * 20.0f;
                        g_ta[row] = -0.95f * tgt - 0.01f * auxs;
                    }
                }
            }
        }
    }

    // ---- barrier reset for graph replay: last CTA to exit zeroes counters
    __syncthreads();
    if (tid == 0) {
        unsigned int r = atomicAdd(&g_done, 1u);
        if (r == GRID - 1) {
            g_bar = 0;
            g_done = 0;
            __threadfence();
        }
    }
}

// ---------------------------------------------------------------------------
// per-row combine of 8 slots -> per-block partials; last block sums them.
// ---------------------------------------------------------------------------
__global__ void reduce_kernel(const int* __restrict__ label,
                              float* __restrict__ out, int out_size) {
    int tid = threadIdx.x;
    int row = blockIdx.x * 256 + tid;
    float sum = 0.0f, m = -1e30f;
    int   ix = -1;
    #pragma unroll
    for (int s = 0; s < NSLOT; ++s) {
        sum += g_psum[s * BS + row];
        float mv = g_pmax[s * BS + row];
        if (mv > m) { m = mv; ix = g_pidx[s * BS + row]; }
    }
    float sl = 20.0f + __logf(sum) + g_ta[row];
    float sc = (ix == label[row]) ? 1.0f : 0.0f;

    #pragma unroll
    for (int o = 16; o > 0; o >>= 1) {
        sl += __shfl_xor_sync(0xffffffffu, sl, o);
        sc += __shfl_xor_sync(0xffffffffu, sc, o);
    }
    __shared__ float a1[8], a2[8];
    __shared__ bool isLast;
    int w = tid >> 5, l = tid & 31;
    if (l == 0) { a1[w] = sl; a2[w] = sc; }
    __syncthreads();
    if (tid == 0) {
        float t1 = 0.0f, t2 = 0.0f;
        #pragma unroll
        for (int k = 0; k < 8; ++k) { t1 += a1[k]; t2 += a2[k]; }
        g_blkl[blockIdx.x] = t1;
        g_blkc[blockIdx.x] = t2;
        __threadfence();
        unsigned int r = atomicAdd(&g_ctr, 1u);
        isLast = (r == NRB - 1);
    }
    __syncthreads();

    if (isLast && tid < NRB) {
        float fl = g_blkl[tid];
        float fc = g_blkc[tid];
        #pragma unroll
        for (int o = 16; o > 0; o >>= 1) {
            fl += __shfl_xor_sync(0xffffffffu, fl, o);
            fc += __shfl_xor_sync(0xffffffffu, fc, o);
        }
        if (l == 0) { a1[w] = fl; a2[w] = fc; }
    }
    if (isLast) __syncthreads();
    if (isLast && tid == 0) {
        out[0] = (a1[0] + a1[1]) * (1.0f / BS);
        if (out_size > 1) out[1] = (a2[0] + a2[1]) * (1.0f / BS);
        g_ctr = 0;                 // reset for graph replay
    }
}

// ---------------------------------------------------------------------------
// host
// ---------------------------------------------------------------------------
extern "C" void kernel_launch(void* const* d_in, const int* in_sizes, int n_in,
                              void* d_out, int out_size) {
    const float* f     = (const float*)d_in[0];
    const float* w     = (const float*)d_in[1];
    const int*   label = (const int*)d_in[2];
    const int*   aux   = (const int*)d_in[3];
    (void)in_sizes; (void)n_in;

    static int configured = 0;
    if (!configured) {
        cudaFuncSetAttribute(gemm_fused,
                             cudaFuncAttributeMaxDynamicSharedMemorySize, DSMEM);
        configured = 1;
    }

    gemm_fused<<<GRID, 256, DSMEM>>>(f, w, label, aux);
    reduce_kernel<<<NRB, 256>>>(label, (float*)d_out, out_size);
}

// round 16
// speedup vs baseline: 1.0399x; 1.0399x over previous
#include <cuda_runtime.h>
#include <cuda_bf16.h>
#include <math.h>
#include <stdint.h>

// ---------------------------------------------------------------------------
// problem constants
// ---------------------------------------------------------------------------
#define BS     16384
#define NC     2000
#define NPADC  2048
#define DIM    512
#define TMR    128              // M rows per tile
#define NCH    256              // classes per N chunk
#define BK     64               // K per stage
#define ROWB   144              // padded smem row stride (72 bf16)
#define ABLK   (128 * ROWB)     // 18432
#define BBLK   (256 * ROWB)     // 36864
#define STG    (ABLK + BBLK)    // 55296
#define NSTG   3
#define DSMEM  (NSTG * STG)     // 165888
#define GRID   148              // persistent CTAs (one per SM)
#define NUNITS 1024             // 128 m-tiles * 8 n-chunks
#define NSLOT  8                // 8 n-chunk partials per row (warpN pre-combined)
#define NRB    64               // reduce blocks
#define K20    28.853900817779268f   // 20 / ln(2)

// ---------------------------------------------------------------------------
// device scratch (allocation-free)
// ---------------------------------------------------------------------------
__device__ float g_ta[BS];
__device__ float g_psum[NSLOT * BS];    // [slot][row] partial exp-sums
__device__ float g_pmax[NSLOT * BS];    // [slot][row] partial maxima
__device__ int   g_pidx[NSLOT * BS];    // [slot][row] partial argmax
__device__ float g_blkl[NRB];           // per-block loss partials
__device__ float g_blkc[NRB];           // per-block acc partials
__device__ unsigned int g_ctr;          // reduce completion counter (zero-init)
__device__ __nv_bfloat16 g_fb[(size_t)BS * DIM];
__device__ __nv_bfloat16 g_wb[(size_t)NPADC * DIM];

// ---------------------------------------------------------------------------
// helpers
// ---------------------------------------------------------------------------
static __device__ __forceinline__ uint32_t sm2u(const void* p) {
    uint32_t a;
    asm("{ .reg .u64 t; cvta.to.shared.u64 t, %1; cvt.u32.u64 %0, t; }"
        : "=r"(a) : "l"(p));
    return a;
}

static __device__ __forceinline__ float ex2f(float x) {
    float y;
    asm("ex2.approx.f32 %0, %1;" : "=f"(y) : "f"(x));
    return y;
}

#define LDSM4(r0, r1, r2, r3, addr) \
    asm volatile("ldmatrix.sync.aligned.m8n8.x4.shared.b16 {%0,%1,%2,%3}, [%4];" \
                 : "=r"(r0), "=r"(r1), "=r"(r2), "=r"(r3) : "r"(addr))

#define MMA16816(d, a, b) \
    asm volatile("mma.sync.aligned.m16n8k16.row.col.f32.bf16.bf16.f32 " \
                 "{%0,%1,%2,%3}, {%4,%5,%6,%7}, {%8,%9}, {%0,%1,%2,%3};" \
                 : "+f"((d)[0]), "+f"((d)[1]), "+f"((d)[2]), "+f"((d)[3]) \
                 : "r"((a)[0]), "r"((a)[1]), "r"((a)[2]), "r"((a)[3]), \
                   "r"((b)[0]), "r"((b)[1]))

#define CPASYNC16(dst, src) \
    asm volatile("cp.async.cg.shared.global [%0], [%1], 16;" :: "r"(dst), "l"(src))

// ---------------------------------------------------------------------------
// prep: 2 rows per warp (MLP=8), rownorm + bf16 convert; f and w together.
// 16 rows per block.  Pad rows (w beyond NC) write zeros via inv=0.
// ---------------------------------------------------------------------------
__global__ void prep_kernel(const float* __restrict__ f, const float* __restrict__ w) {
    int warp = threadIdx.x >> 5;
    int lane = threadIdx.x & 31;
    int base = blockIdx.x * 16 + warp * 2;

    const float* xs[2];
    __nv_bfloat16* outs[2];
    bool pad[2];
    #pragma unroll
    for (int r = 0; r < 2; ++r) {
        int row = base + r;
        if (row < BS) {
            xs[r] = f + (size_t)row * DIM;
            outs[r] = g_fb + (size_t)row * DIM;
            pad[r] = false;
        } else {
            int wr = row - BS;
            outs[r] = g_wb + (size_t)wr * DIM;
            pad[r] = (wr >= NC);
            xs[r] = pad[r] ? f : (w + (size_t)wr * DIM);   // dummy valid ptr if pad
        }
    }

    float4 v[2][4];
    float s[2] = {0.0f, 0.0f};
    #pragma unroll
    for (int r = 0; r < 2; ++r) {
        const float4* p = reinterpret_cast<const float4*>(xs[r]);
        #pragma unroll
        for (int k = 0; k < 4; ++k) v[r][k] = p[lane + 32 * k];
    }
    #pragma unroll
    for (int r = 0; r < 2; ++r)
        #pragma unroll
        for (int k = 0; k < 4; ++k)
            s[r] += v[r][k].x * v[r][k].x + v[r][k].y * v[r][k].y
                  + v[r][k].z * v[r][k].z + v[r][k].w * v[r][k].w;
    #pragma unroll
    for (int o = 16; o > 0; o >>= 1) {
        s[0] += __shfl_xor_sync(0xffffffffu, s[0], o);
        s[1] += __shfl_xor_sync(0xffffffffu, s[1], o);
    }
    #pragma unroll
    for (int r = 0; r < 2; ++r) {
        float inv = pad[r] ? 0.0f : (1.0f / fmaxf(sqrtf(s[r]), 1e-12f));
        uint2* dp = reinterpret_cast<uint2*>(outs[r]);
        #pragma unroll
        for (int k = 0; k < 4; ++k) {
            __nv_bfloat162 h0 = __floats2bfloat162_rn(v[r][k].x * inv, v[r][k].y * inv);
            __nv_bfloat162 h1 = __floats2bfloat162_rn(v[r][k].z * inv, v[r][k].w * inv);
            uint2 u;
            u.x = *reinterpret_cast<uint32_t*>(&h0);
            u.y = *reinterpret_cast<uint32_t*>(&h1);
            dp[lane + 32 * k] = u;
        }
    }
}

// ---------------------------------------------------------------------------
// persistent fused bf16 mma.sync GEMM + fixed-max partial softmax (MUFU exp)
// + distributed tgt/aux gather (16 rows per unit, 2 per warp).
// ---------------------------------------------------------------------------
__global__ void __launch_bounds__(256, 1)
gemm_fused(const int* __restrict__ label, const int* __restrict__ aux) {
    extern __shared__ char dsm[];
    __shared__ float sredS[4][TMR];
    __shared__ float sredM[4][TMR];
    __shared__ int   sredI[4][TMR];

    const int tid   = threadIdx.x;
    const int lane  = tid & 31;
    const int wid   = tid >> 5;
    const int warpM = wid & 1;     // rows warpM*64
    const int warpN = wid >> 1;    // cols warpN*64
    const uint32_t sbase = sm2u(dsm);
    const int cta = blockIdx.x;
    const int myUnits = (NUNITS - cta + GRID - 1) / GRID;   // 7 or 6
    const int S = myUnits * 8;

    const uint32_t aoff = (uint32_t)(warpM * 64 + (lane & 15)) * ROWB
                        + (uint32_t)(lane >> 4) * 16;
    const uint32_t boff = (uint32_t)(warpN * 64 + (lane & 7) + ((lane >> 4) << 3)) * ROWB
                        + (uint32_t)((lane >> 3) & 1) * 16;

    float acc[4][8][4];            // [mt][n8][j]
    float vsum[4][2];
    float vmax[4][2];
    int   vidx[4][2];

    auto load_stage = [&](int s, int slot) {
        const int u  = cta + (s >> 3) * GRID;
        const int kb = s & 7;
        const int mtile = u & 127, nch = u >> 7;
        const uint32_t sb = sbase + (uint32_t)slot * STG;
        const __nv_bfloat16* Asrc = g_fb + (size_t)(mtile * TMR) * DIM + kb * BK;
        const __nv_bfloat16* Bsrc = g_wb + (size_t)(nch * NCH) * DIM + kb * BK;
        #pragma unroll
        for (int i = 0; i < 4; ++i) {          // A: 1024 chunks
            int ch = tid + 256 * i;
            int row = ch >> 3, c8 = ch & 7;
            CPASYNC16(sb + (uint32_t)row * ROWB + c8 * 16,
                      Asrc + (size_t)row * DIM + c8 * 8);
        }
        #pragma unroll
        for (int i = 0; i < 8; ++i) {          // B: 2048 chunks
            int ch = tid + 256 * i;
            int row = ch >> 3, c8 = ch & 7;
            CPASYNC16(sb + ABLK + (uint32_t)row * ROWB + c8 * 16,
                      Bsrc + (size_t)row * DIM + c8 * 8);
        }
        asm volatile("cp.async.commit_group;" ::: "memory");
    };

    load_stage(0, 0);
    load_stage(1, 1);

    int csSlot = 0, ldSlot = 2;
    for (int t = 0; t < S; ++t) {
        if (t + 1 < S) {
            asm volatile("cp.async.wait_group 1;" ::: "memory");
        } else {
            asm volatile("cp.async.wait_group 0;" ::: "memory");
        }
        __syncthreads();
        if (t + 2 < S) {
            load_stage(t + 2, ldSlot);
            if (++ldSlot == NSTG) ldSlot = 0;
        }

        if ((t & 7) == 0) {
            #pragma unroll
            for (int mt = 0; mt < 4; ++mt) {
                #pragma unroll
                for (int n8 = 0; n8 < 8; ++n8)
                    #pragma unroll
                    for (int j = 0; j < 4; ++j) acc[mt][n8][j] = 0.0f;
                #pragma unroll
                for (int rh = 0; rh < 2; ++rh) {
                    vsum[mt][rh] = 0.0f; vmax[mt][rh] = -1e30f; vidx[mt][rh] = -1;
                }
            }
        }

        const uint32_t sb = sbase + (uint32_t)csSlot * STG;
        if (++csSlot == NSTG) csSlot = 0;
        const uint32_t aS = sb + aoff;
        const uint32_t bS = sb + ABLK + boff;
        #pragma unroll
        for (int kk = 0; kk < 4; ++kk) {
            uint32_t Af[4][4];
            #pragma unroll
            for (int mt = 0; mt < 4; ++mt)
                LDSM4(Af[mt][0], Af[mt][1], Af[mt][2], Af[mt][3],
                      aS + (uint32_t)mt * 16 * ROWB + kk * 32);
            uint32_t Bf[8][2];
            #pragma unroll
            for (int nt = 0; nt < 4; ++nt) {
                uint32_t r0, r1, r2, r3;
                LDSM4(r0, r1, r2, r3, bS + (uint32_t)nt * 16 * ROWB + kk * 32);
                Bf[2 * nt][0] = r0;     Bf[2 * nt][1] = r1;
                Bf[2 * nt + 1][0] = r2; Bf[2 * nt + 1][1] = r3;
            }
            #pragma unroll
            for (int mt = 0; mt < 4; ++mt)
                #pragma unroll
                for (int n8 = 0; n8 < 8; ++n8)
                    MMA16816(acc[mt][n8], Af[mt], Bf[n8]);
        }

        if ((t & 7) == 7) {
            const int u = cta + (t >> 3) * GRID;
            const int mtile = u & 127, nch = u >> 7;
            const int ncBase = nch * NCH + warpN * 64;
            if (ncBase + 64 <= NC) {
                #pragma unroll
                for (int mt = 0; mt < 4; ++mt) {
                    #pragma unroll
                    for (int n8 = 0; n8 < 8; ++n8) {
                        #pragma unroll
                        for (int j = 0; j < 4; ++j) {
                            int cls = ncBase + n8 * 8 + (lane & 3) * 2 + (j & 1);
                            float v  = acc[mt][n8][j];
                            int   rh = j >> 1;
                            if (v > vmax[mt][rh]) { vmax[mt][rh] = v; vidx[mt][rh] = cls; }
                            vsum[mt][rh] += ex2f(fmaf(v, K20, -K20));
                        }
                    }
                }
            } else {
                #pragma unroll
                for (int mt = 0; mt < 4; ++mt) {
                    #pragma unroll
                    for (int n8 = 0; n8 < 8; ++n8) {
                        #pragma unroll
                        for (int j = 0; j < 4; ++j) {
                            int cls = ncBase + n8 * 8 + (lane & 3) * 2 + (j & 1);
                            if (cls < NC) {
                                float v  = acc[mt][n8][j];
                                int   rh = j >> 1;
                                if (v > vmax[mt][rh]) { vmax[mt][rh] = v; vidx[mt][rh] = cls; }
                                vsum[mt][rh] += ex2f(fmaf(v, K20, -K20));
                            }
                        }
                    }
                }
            }
            #pragma unroll
            for (int mt = 0; mt < 4; ++mt) {
                #pragma unroll
                for (int rh = 0; rh < 2; ++rh) {
                    float s = vsum[mt][rh], m = vmax[mt][rh];
                    int   ix = vidx[mt][rh];
                    #pragma unroll
                    for (int o = 1; o <= 2; o <<= 1) {
                        float so = __shfl_xor_sync(0xffffffffu, s, o);
                        float mo = __shfl_xor_sync(0xffffffffu, m, o);
                        int   io = __shfl_xor_sync(0xffffffffu, ix, o);
                        s += so;
                        if (mo > m) { m = mo; ix = io; }
                    }
                    if ((lane & 3) == 0) {
                        int r = warpM * 64 + mt * 16 + rh * 8 + (lane >> 2);
                        sredS[warpN][r] = s;
                        sredM[warpN][r] = m;
                        sredI[warpN][r] = ix;
                    }
                }
            }
            __syncthreads();
            if (tid < TMR) {
                float s = sredS[0][tid], m = sredM[0][tid];
                int   ix = sredI[0][tid];
                #pragma unroll
                for (int wn = 1; wn < 4; ++wn) {
                    s += sredS[wn][tid];
                    float mw = sredM[wn][tid];
                    if (mw > m) { m = mw; ix = sredI[wn][tid]; }
                }
                int row = mtile * TMR + tid;
                g_psum[nch * BS + row] = s;
                g_pmax[nch * BS + row] = m;
                g_pidx[nch * BS + row] = ix;
            }

            // ---- distributed gather: rows [u*16, u*16+16), 2 per warp ----
            {
                const int grow0 = u * 16 + wid * 2;
                #pragma unroll
                for (int r = 0; r < 2; ++r) {
                    const int row = grow0 + r;
                    const uint32_t* fr = reinterpret_cast<const uint32_t*>(
                        g_fb + (size_t)row * DIM);
                    uint32_t ff[8];
                    #pragma unroll
                    for (int k = 0; k < 8; ++k) ff[k] = fr[lane + 32 * k];
                    float acc6[6];
                    #pragma unroll
                    for (int c = 0; c < 6; ++c) {
                        int cls = (c == 0) ? label[row] : aux[row * 5 + c - 1];
                        const uint32_t* wr2 = reinterpret_cast<const uint32_t*>(
                            g_wb + (size_t)cls * DIM);
                        float s = 0.0f;
                        #pragma unroll
                        for (int k = 0; k < 8; ++k) {
                            uint32_t wp = wr2[lane + 32 * k];
                            float2 fa = __bfloat1622float2(
                                *reinterpret_cast<__nv_bfloat162*>(&ff[k]));
                            float2 wa = __bfloat1622float2(
                                *reinterpret_cast<__nv_bfloat162*>(&wp));
                            s = fmaf(fa.x, wa.x, s);
                            s = fmaf(fa.y, wa.y, s);
                        }
                        #pragma unroll
                        for (int o = 16; o > 0; o >>= 1)
                            s += __shfl_xor_sync(0xffffffffu, s, o);
                        acc6[c] = s;
                    }
                    if (lane == 0) {
                        float tgt  = acc6[0] * 20.0f;
                        float auxs = (acc6[1] + acc6[2] + acc6[3]
                                    + acc6[4] + acc6[5]) * 20.0f;
                        g_ta[row] = -0.95f * tgt - 0.01f * auxs;
                    }
                }
            }
        }
    }
}

// ---------------------------------------------------------------------------
// per-row combine of 8 slots -> per-block partials; last block sums them.
// ---------------------------------------------------------------------------
__global__ void reduce_kernel(const int* __restrict__ label,
                              float* __restrict__ out, int out_size) {
    int tid = threadIdx.x;
    int row = blockIdx.x * 256 + tid;
    float sum = 0.0f, m = -1e30f;
    int   ix = -1;
    #pragma unroll
    for (int s = 0; s < NSLOT; ++s) {
        sum += g_psum[s * BS + row];
        float mv = g_pmax[s * BS + row];
        if (mv > m) { m = mv; ix = g_pidx[s * BS + row]; }
    }
    float sl = 20.0f + __logf(sum) + g_ta[row];
    float sc = (ix == label[row]) ? 1.0f : 0.0f;

    #pragma unroll
    for (int o = 16; o > 0; o >>= 1) {
        sl += __shfl_xor_sync(0xffffffffu, sl, o);
        sc += __shfl_xor_sync(0xffffffffu, sc, o);
    }
    __shared__ float a1[8], a2[8];
    __shared__ bool isLast;
    int w = tid >> 5, l = tid & 31;
    if (l == 0) { a1[w] = sl; a2[w] = sc; }
    __syncthreads();
    if (tid == 0) {
        float t1 = 0.0f, t2 = 0.0f;
        #pragma unroll
        for (int k = 0; k < 8; ++k) { t1 += a1[k]; t2 += a2[k]; }
        g_blkl[blockIdx.x] = t1;
        g_blkc[blockIdx.x] = t2;
        __threadfence();
        unsigned int r = atomicAdd(&g_ctr, 1u);
        isLast = (r == NRB - 1);
    }
    __syncthreads();

    if (isLast && tid < NRB) {
        float fl = g_blkl[tid];
        float fc = g_blkc[tid];
        #pragma unroll
        for (int o = 16; o > 0; o >>= 1) {
            fl += __shfl_xor_sync(0xffffffffu, fl, o);
            fc += __shfl_xor_sync(0xffffffffu, fc, o);
        }
        if (l == 0) { a1[w] = fl; a2[w] = fc; }
    }
    if (isLast) __syncthreads();
    if (isLast && tid == 0) {
        out[0] = (a1[0] + a1[1]) * (1.0f / BS);
        if (out_size > 1) out[1] = (a2[0] + a2[1]) * (1.0f / BS);
        g_ctr = 0;                 // reset for graph replay
    }
}

// ---------------------------------------------------------------------------
// host
// ---------------------------------------------------------------------------
extern "C" void kernel_launch(void* const* d_in, const int* in_sizes, int n_in,
                              void* d_out, int out_size) {
    const float* f     = (const float*)d_in[0];
    const float* w     = (const float*)d_in[1];
    const int*   label = (const int*)d_in[2];
    const int*   aux   = (const int*)d_in[3];
    (void)in_sizes; (void)n_in;

    static int configured = 0;
    if (!configured) {
        cudaFuncSetAttribute(gemm_fused,
                             cudaFuncAttributeMaxDynamicSharedMemorySize, DSMEM);
        configured = 1;
    }

    prep_kernel<<<(BS + NPADC) / 16, 256>>>(f, w);
    gemm_fused<<<GRID, 256, DSMEM>>>(label, aux);
    reduce_kernel<<<NRB, 256>>>(label, (float*)d_out, out_size);
}

// round 17
// speedup vs baseline: 1.0413x; 1.0013x over previous
#include <cuda_runtime.h>
#include <cuda_bf16.h>
#include <math.h>
#include <stdint.h>

// ---------------------------------------------------------------------------
// problem constants
// ---------------------------------------------------------------------------
#define BS     16384
#define NC     2000
#define NPADC  2048
#define DIM    512
#define TMR    128              // M rows per tile
#define NCH    256              // classes per N chunk
#define BK     64               // K per stage
#define ROWB   144              // padded smem row stride (72 bf16)
#define ABLK   (128 * ROWB)     // 18432
#define BBLK   (256 * ROWB)     // 36864
#define STG    (ABLK + BBLK)    // 55296
#define NSTG   3
#define DSMEM  (NSTG * STG)     // 165888
#define GRID   148              // persistent CTAs (one per SM)
#define NUNITS 1024             // 128 m-tiles * 8 n-chunks
#define NSLOT  8                // 8 n-chunk partials per row (warpN pre-combined)
#define NRB    64               // reduce blocks
#define K20    28.853900817779268f   // 20 / ln(2)

// ---------------------------------------------------------------------------
// device scratch (allocation-free)
// ---------------------------------------------------------------------------
__device__ float g_ta[BS];
__device__ float g_psum[NSLOT * BS];    // [slot][row] partial exp-sums
__device__ float g_pmax[NSLOT * BS];    // [slot][row] partial maxima
__device__ int   g_pidx[NSLOT * BS];    // [slot][row] partial argmax
__device__ float g_blkl[NRB];           // per-block loss partials
__device__ float g_blkc[NRB];           // per-block acc partials
__device__ unsigned int g_ctr;          // reduce completion counter (zero-init)
__device__ __nv_bfloat16 g_fb[(size_t)BS * DIM];
__device__ __nv_bfloat16 g_wb[(size_t)NPADC * DIM];

// ---------------------------------------------------------------------------
// helpers
// ---------------------------------------------------------------------------
static __device__ __forceinline__ uint32_t sm2u(const void* p) {
    uint32_t a;
    asm("{ .reg .u64 t; cvta.to.shared.u64 t, %1; cvt.u32.u64 %0, t; }"
        : "=r"(a) : "l"(p));
    return a;
}

static __device__ __forceinline__ float ex2f(float x) {
    float y;
    asm("ex2.approx.f32 %0, %1;" : "=f"(y) : "f"(x));
    return y;
}

static __device__ __forceinline__ float4 ldcs4(const float4* p) {
    float4 v;
    asm("ld.global.cs.v4.f32 {%0,%1,%2,%3}, [%4];"
        : "=f"(v.x), "=f"(v.y), "=f"(v.z), "=f"(v.w) : "l"(p));
    return v;
}

#define LDSM4(r0, r1, r2, r3, addr) \
    asm volatile("ldmatrix.sync.aligned.m8n8.x4.shared.b16 {%0,%1,%2,%3}, [%4];" \
                 : "=r"(r0), "=r"(r1), "=r"(r2), "=r"(r3) : "r"(addr))

#define MMA16816(d, a, b) \
    asm volatile("mma.sync.aligned.m16n8k16.row.col.f32.bf16.bf16.f32 " \
                 "{%0,%1,%2,%3}, {%4,%5,%6,%7}, {%8,%9}, {%0,%1,%2,%3};" \
                 : "+f"((d)[0]), "+f"((d)[1]), "+f"((d)[2]), "+f"((d)[3]) \
                 : "r"((a)[0]), "r"((a)[1]), "r"((a)[2]), "r"((a)[3]), \
                   "r"((b)[0]), "r"((b)[1]))

#define CPASYNC16(dst, src) \
    asm volatile("cp.async.cg.shared.global [%0], [%1], 16;" :: "r"(dst), "l"(src))

// ---------------------------------------------------------------------------
// prep: warp-per-row rownorm + bf16 convert; f and w in one launch.
// f32 source read with streaming (evict-first) policy — single use.
// ---------------------------------------------------------------------------
__global__ void prep_kernel(const float* __restrict__ f, const float* __restrict__ w) {
    int warp = threadIdx.x >> 5;
    int lane = threadIdx.x & 31;
    int b    = blockIdx.x;

    const float* x;
    __nv_bfloat16* out;
    int row;
    if (b < BS / 8) {
        row = b * 8 + warp;
        x = f + (size_t)row * DIM;
        out = g_fb + (size_t)row * DIM;
    } else {
        row = (b - BS / 8) * 8 + warp;
        out = g_wb + (size_t)row * DIM;
        if (row >= NC) {
            uint2 z; z.x = 0u; z.y = 0u;
            uint2* dp = reinterpret_cast<uint2*>(out);
            #pragma unroll
            for (int k = 0; k < 4; ++k) dp[lane + 32 * k] = z;
            return;
        }
        x = w + (size_t)row * DIM;
    }

    const float4* p = reinterpret_cast<const float4*>(x);
    float4 v[4];
    float s = 0.0f;
    #pragma unroll
    for (int k = 0; k < 4; ++k) {
        v[k] = ldcs4(p + lane + 32 * k);
        s += v[k].x * v[k].x + v[k].y * v[k].y + v[k].z * v[k].z + v[k].w * v[k].w;
    }
    #pragma unroll
    for (int o = 16; o > 0; o >>= 1) s += __shfl_xor_sync(0xffffffffu, s, o);
    float inv = 1.0f / fmaxf(sqrtf(s), 1e-12f);
    uint2* dp = reinterpret_cast<uint2*>(out);
    #pragma unroll
    for (int k = 0; k < 4; ++k) {
        __nv_bfloat162 h0 = __floats2bfloat162_rn(v[k].x * inv, v[k].y * inv);
        __nv_bfloat162 h1 = __floats2bfloat162_rn(v[k].z * inv, v[k].w * inv);
        uint2 u;
        u.x = *reinterpret_cast<uint32_t*>(&h0);
        u.y = *reinterpret_cast<uint32_t*>(&h1);
        dp[lane + 32 * k] = u;
    }
}

// ---------------------------------------------------------------------------
// persistent fused bf16 mma.sync GEMM + fixed-max partial softmax (MUFU exp)
// + distributed tgt/aux gather (16 rows per unit, 2 per warp).
// ---------------------------------------------------------------------------
__global__ void __launch_bounds__(256, 1)
gemm_fused(const int* __restrict__ label, const int* __restrict__ aux) {
    extern __shared__ char dsm[];
    __shared__ float sredS[4][TMR];
    __shared__ float sredM[4][TMR];
    __shared__ int   sredI[4][TMR];

    const int tid   = threadIdx.x;
    const int lane  = tid & 31;
    const int wid   = tid >> 5;
    const int warpM = wid & 1;     // rows warpM*64
    const int warpN = wid >> 1;    // cols warpN*64
    const uint32_t sbase = sm2u(dsm);
    const int cta = blockIdx.x;
    const int myUnits = (NUNITS - cta + GRID - 1) / GRID;   // 7 or 6
    const int S = myUnits * 8;

    const uint32_t aoff = (uint32_t)(warpM * 64 + (lane & 15)) * ROWB
                        + (uint32_t)(lane >> 4) * 16;
    const uint32_t boff = (uint32_t)(warpN * 64 + (lane & 7) + ((lane >> 4) << 3)) * ROWB
                        + (uint32_t)((lane >> 3) & 1) * 16;

    float acc[4][8][4];            // [mt][n8][j]
    float vsum[4][2];
    float vmax[4][2];
    int   vidx[4][2];

    auto load_stage = [&](int s, int slot) {
        const int u  = cta + (s >> 3) * GRID;
        const int kb = s & 7;
        const int mtile = u & 127, nch = u >> 7;
        const uint32_t sb = sbase + (uint32_t)slot * STG;
        const __nv_bfloat16* Asrc = g_fb + (size_t)(mtile * TMR) * DIM + kb * BK;
        const __nv_bfloat16* Bsrc = g_wb + (size_t)(nch * NCH) * DIM + kb * BK;
        #pragma unroll
        for (int i = 0; i < 4; ++i) {          // A: 1024 chunks
            int ch = tid + 256 * i;
            int row = ch >> 3, c8 = ch & 7;
            CPASYNC16(sb + (uint32_t)row * ROWB + c8 * 16,
                      Asrc + (size_t)row * DIM + c8 * 8);
        }
        #pragma unroll
        for (int i = 0; i < 8; ++i) {          // B: 2048 chunks
            int ch = tid + 256 * i;
            int row = ch >> 3, c8 = ch & 7;
            CPASYNC16(sb + ABLK + (uint32_t)row * ROWB + c8 * 16,
                      Bsrc + (size_t)row * DIM + c8 * 8);
        }
        asm volatile("cp.async.commit_group;" ::: "memory");
    };

    load_stage(0, 0);
    load_stage(1, 1);

    int csSlot = 0, ldSlot = 2;
    for (int t = 0; t < S; ++t) {
        if (t + 1 < S) {
            asm volatile("cp.async.wait_group 1;" ::: "memory");
        } else {
            asm volatile("cp.async.wait_group 0;" ::: "memory");
        }
        __syncthreads();
        if (t + 2 < S) {
            load_stage(t + 2, ldSlot);
            if (++ldSlot == NSTG) ldSlot = 0;
        }

        if ((t & 7) == 0) {
            #pragma unroll
            for (int mt = 0; mt < 4; ++mt) {
                #pragma unroll
                for (int n8 = 0; n8 < 8; ++n8)
                    #pragma unroll
                    for (int j = 0; j < 4; ++j) acc[mt][n8][j] = 0.0f;
                #pragma unroll
                for (int rh = 0; rh < 2; ++rh) {
                    vsum[mt][rh] = 0.0f; vmax[mt][rh] = -1e30f; vidx[mt][rh] = -1;
                }
            }
        }

        const uint32_t sb = sbase + (uint32_t)csSlot * STG;
        if (++csSlot == NSTG) csSlot = 0;
        const uint32_t aS = sb + aoff;
        const uint32_t bS = sb + ABLK + boff;
        #pragma unroll
        for (int kk = 0; kk < 4; ++kk) {
            uint32_t Af[4][4];
            #pragma unroll
            for (int mt = 0; mt < 4; ++mt)
                LDSM4(Af[mt][0], Af[mt][1], Af[mt][2], Af[mt][3],
                      aS + (uint32_t)mt * 16 * ROWB + kk * 32);
            uint32_t Bf[8][2];
            #pragma unroll
            for (int nt = 0; nt < 4; ++nt) {
                uint32_t r0, r1, r2, r3;
                LDSM4(r0, r1, r2, r3, bS + (uint32_t)nt * 16 * ROWB + kk * 32);
                Bf[2 * nt][0] = r0;     Bf[2 * nt][1] = r1;
                Bf[2 * nt + 1][0] = r2; Bf[2 * nt + 1][1] = r3;
            }
            #pragma unroll
            for (int mt = 0; mt < 4; ++mt)
                #pragma unroll
                for (int n8 = 0; n8 < 8; ++n8)
                    MMA16816(acc[mt][n8], Af[mt], Bf[n8]);
        }

        if ((t & 7) == 7) {
            const int u = cta + (t >> 3) * GRID;
            const int mtile = u & 127, nch = u >> 7;
            const int ncBase = nch * NCH + warpN * 64;
            if (ncBase + 64 <= NC) {
                #pragma unroll
                for (int mt = 0; mt < 4; ++mt) {
                    #pragma unroll
                    for (int n8 = 0; n8 < 8; ++n8) {
                        #pragma unroll
                        for (int j = 0; j < 4; ++j) {
                            int cls = ncBase + n8 * 8 + (lane & 3) * 2 + (j & 1);
                            float v  = acc[mt][n8][j];
                            int   rh = j >> 1;
                            if (v > vmax[mt][rh]) { vmax[mt][rh] = v; vidx[mt][rh] = cls; }
                            vsum[mt][rh] += ex2f(fmaf(v, K20, -K20));
                        }
                    }
                }
            } else {
                #pragma unroll
                for (int mt = 0; mt < 4; ++mt) {
                    #pragma unroll
                    for (int n8 = 0; n8 < 8; ++n8) {
                        #pragma unroll
                        for (int j = 0; j < 4; ++j) {
                            int cls = ncBase + n8 * 8 + (lane & 3) * 2 + (j & 1);
                            if (cls < NC) {
                                float v  = acc[mt][n8][j];
                                int   rh = j >> 1;
                                if (v > vmax[mt][rh]) { vmax[mt][rh] = v; vidx[mt][rh] = cls; }
                                vsum[mt][rh] += ex2f(fmaf(v, K20, -K20));
                            }
                        }
                    }
                }
            }
            #pragma unroll
            for (int mt = 0; mt < 4; ++mt) {
                #pragma unroll
                for (int rh = 0; rh < 2; ++rh) {
                    float s = vsum[mt][rh], m = vmax[mt][rh];
                    int   ix = vidx[mt][rh];
                    #pragma unroll
                    for (int o = 1; o <= 2; o <<= 1) {
                        float so = __shfl_xor_sync(0xffffffffu, s, o);
                        float mo = __shfl_xor_sync(0xffffffffu, m, o);
                        int   io = __shfl_xor_sync(0xffffffffu, ix, o);
                        s += so;
                        if (mo > m) { m = mo; ix = io; }
                    }
                    if ((lane & 3) == 0) {
                        int r = warpM * 64 + mt * 16 + rh * 8 + (lane >> 2);
                        sredS[warpN][r] = s;
                        sredM[warpN][r] = m;
                        sredI[warpN][r] = ix;
                    }
                }
            }
            __syncthreads();
            if (tid < TMR) {
                float s = sredS[0][tid], m = sredM[0][tid];
                int   ix = sredI[0][tid];
                #pragma unroll
                for (int wn = 1; wn < 4; ++wn) {
                    s += sredS[wn][tid];
                    float mw = sredM[wn][tid];
                    if (mw > m) { m = mw; ix = sredI[wn][tid]; }
                }
                int row = mtile * TMR + tid;
                g_psum[nch * BS + row] = s;
                g_pmax[nch * BS + row] = m;
                g_pidx[nch * BS + row] = ix;
            }

            // ---- distributed gather: rows [u*16, u*16+16), 2 per warp ----
            {
                const int grow0 = u * 16 + wid * 2;
                #pragma unroll
                for (int r = 0; r < 2; ++r) {
                    const int row = grow0 + r;
                    const uint32_t* fr = reinterpret_cast<const uint32_t*>(
                        g_fb + (size_t)row * DIM);
                    uint32_t ff[8];
                    #pragma unroll
                    for (int k = 0; k < 8; ++k) ff[k] = fr[lane + 32 * k];
                    float acc6[6];
                    #pragma unroll
                    for (int c = 0; c < 6; ++c) {
                        int cls = (c == 0) ? label[row] : aux[row * 5 + c - 1];
                        const uint32_t* wr2 = reinterpret_cast<const uint32_t*>(
                            g_wb + (size_t)cls * DIM);
                        float s = 0.0f;
                        #pragma unroll
                        for (int k = 0; k < 8; ++k) {
                            uint32_t wp = wr2[lane + 32 * k];
                            float2 fa = __bfloat1622float2(
                                *reinterpret_cast<__nv_bfloat162*>(&ff[k]));
                            float2 wa = __bfloat1622float2(
                                *reinterpret_cast<__nv_bfloat162*>(&wp));
                            s = fmaf(fa.x, wa.x, s);
                            s = fmaf(fa.y, wa.y, s);
                        }
                        #pragma unroll
                        for (int o = 16; o > 0; o >>= 1)
                            s += __shfl_xor_sync(0xffffffffu, s, o);
                        acc6[c] = s;
                    }
                    if (lane == 0) {
                        float tgt  = acc6[0] * 20.0f;
                        float auxs = (acc6[1] + acc6[2] + acc6[3]
                                    + acc6[4] + acc6[5]) * 20.0f;
                        g_ta[row] = -0.95f * tgt - 0.01f * auxs;
                    }
                }
            }
        }
    }
}

// ---------------------------------------------------------------------------
// per-row combine of 8 slots -> per-block partials; last block sums them.
// ---------------------------------------------------------------------------
__global__ void reduce_kernel(const int* __restrict__ label,
                              float* __restrict__ out, int out_size) {
    int tid = threadIdx.x;
    int row = blockIdx.x * 256 + tid;
    float sum = 0.0f, m = -1e30f;
    int   ix = -1;
    #pragma unroll
    for (int s = 0; s < NSLOT; ++s) {
        sum += g_psum[s * BS + row];
        float mv = g_pmax[s * BS + row];
        if (mv > m) { m = mv; ix = g_pidx[s * BS + row]; }
    }
    float sl = 20.0f + __logf(sum) + g_ta[row];
    float sc = (ix == label[row]) ? 1.0f : 0.0f;

    #pragma unroll
    for (int o = 16; o > 0; o >>= 1) {
        sl += __shfl_xor_sync(0xffffffffu, sl, o);
        sc += __shfl_xor_sync(0xffffffffu, sc, o);
    }
    __shared__ float a1[8], a2[8];
    __shared__ bool isLast;
    int w = tid >> 5, l = tid & 31;
    if (l == 0) { a1[w] = sl; a2[w] = sc; }
    __syncthreads();
    if (tid == 0) {
        float t1 = 0.0f, t2 = 0.0f;
        #pragma unroll
        for (int k = 0; k < 8; ++k) { t1 += a1[k]; t2 += a2[k]; }
        g_blkl[blockIdx.x] = t1;
        g_blkc[blockIdx.x] = t2;
        __threadfence();
        unsigned int r = atomicAdd(&g_ctr, 1u);
        isLast = (r == NRB - 1);
    }
    __syncthreads();

    if (isLast && tid < NRB) {
        float fl = g_blkl[tid];
        float fc = g_blkc[tid];
        #pragma unroll
        for (int o = 16; o > 0; o >>= 1) {
            fl += __shfl_xor_sync(0xffffffffu, fl, o);
            fc += __shfl_xor_sync(0xffffffffu, fc, o);
        }
        if (l == 0) { a1[w] = fl; a2[w] = fc; }
    }
    if (isLast) __syncthreads();
    if (isLast && tid == 0) {
        out[0] = (a1[0] + a1[1]) * (1.0f / BS);
        if (out_size > 1) out[1] = (a2[0] + a2[1]) * (1.0f / BS);
        g_ctr = 0;                 // reset for graph replay
    }
}

// ---------------------------------------------------------------------------
// host
// ---------------------------------------------------------------------------
extern "C" void kernel_launch(void* const* d_in, const int* in_sizes, int n_in,
                              void* d_out, int out_size) {
    const float* f     = (const float*)d_in[0];
    const float* w     = (const float*)d_in[1];
    const int*   label = (const int*)d_in[2];
    const int*   aux   = (const int*)d_in[3];
    (void)in_sizes; (void)n_in;

    static int configured = 0;
    if (!configured) {
        cudaFuncSetAttribute(gemm_fused,
                             cudaFuncAttributeMaxDynamicSharedMemorySize, DSMEM);
        configured = 1;
    }

    prep_kernel<<<BS / 8 + NPADC / 8, 256>>>(f, w);
    gemm_fused<<<GRID, 256, DSMEM>>>(label, aux);
    reduce_kernel<<<NRB, 256>>>(label, (float*)d_out, out_size);
}